// round 16
// baseline (speedup 1.0000x reference)
#include <cuda_runtime.h>
#include <cuda_fp16.h>
#include <math.h>

// SlowROIPool R16: fix the R15 carveout trap (7x30KB smem left ~18KB L1D ->
// plane reads were L2 hits @~240cyc). Blocks now copy their PRE-CONVERTED
// fp16 2-channel plane (14KB) into smem (3.5 LDG.128+STS.128 per thread) and
// pool from LDS @29cyc. 7 blocks/SM, 56 warps/SM, grid 1024 single wave.
// Unified narrow/wide bin loop (lane-mapping differs only).
// images: [8,128,56,56] f32, rois: [512,4] f32, roi_idx: [512] i32,
// out: [512,128,7,7] f32.

#define OUT_D 7
#define ROWH4    16                 // H4 (8B) units per plane row (64 halves)
#define PLANE_H4 (56 * ROWH4)       // 896 H4 units per (b,c) plane

// fp16 planes: 1024 planes x 56 rows x 64 halves (+pad for overread)
__device__ __align__(16) unsigned long long g_plane[1024 * PLANE_H4 + 32];

__device__ int        g_meta[512];  // roi | cp0q<<16 | narrow<<24
__device__ ulonglong2 g_ybin[512];  // {ysP, nP}: byte i = ys / row-count of y-bin i
__device__ ulonglong2 g_xbin[512];  // {xsP, xeP}: byte j = half-index bounds (frac3-based)
__device__ int        g_start[9];   // per-image segment starts

// ---- fused: fp32->fp16 conversion (blocks 0..783, 2 float4/thread) + prep ----
__global__ void prep_convert_kernel(const float* __restrict__ images,
                                    const float* __restrict__ rois,
                                    const int*   __restrict__ roi_idx)
{
    if (blockIdx.x < 784) {
        // 784 blocks x 512 threads x 2 = 802816 float4 (exact)
        const int j0 = blockIdx.x * 1024 + threadIdx.x;
        #pragma unroll
        for (int t = 0; t < 2; t++) {
            const int j = j0 + t * 512;
            float4 v = reinterpret_cast<const float4*>(images)[j];
            const int r  = j / 14;                  // global row = plane*56 + y
            const int c4 = j - r * 14;
            __half2 lo = __floats2half2_rn(v.x, v.y);
            __half2 hi = __floats2half2_rn(v.z, v.w);
            uint2 w;
            w.x = *reinterpret_cast<unsigned*>(&lo);
            w.y = *reinterpret_cast<unsigned*>(&hi);
            reinterpret_cast<uint2*>(g_plane)[r * ROWH4 + c4] = w;
        }
        return;
    }

    // ---- prep (block 784, 512 threads) ----
    __shared__ int cnt[8];
    __shared__ int base[8];
    __shared__ int hist[8][128];
    const int tid = threadIdx.x;
    if (tid < 8) cnt[tid] = 0;
    for (int i = tid; i < 8 * 128; i += 512) (&hist[0][0])[i] = 0;
    __syncthreads();
    const int img = roi_idx[tid];
    atomicAdd(&cnt[img], 1);
    __syncthreads();
    if (tid == 0) {
        int acc = 0;
        for (int i = 0; i < 8; i++) { base[i] = acc; g_start[i] = acc; acc += cnt[i]; }
        g_start[8] = acc;
    }
    __syncthreads();

    const float4 box = reinterpret_cast<const float4*>(rois)[tid];
    // Match jnp: fp32 floor/ceil then int cast.
    const int x1 = (int)floorf(box.x * 56.0f);
    const int y1 = (int)floorf(box.y * 56.0f);
    const int x2 = (int)ceilf (box.z * 56.0f);
    const int y2 = (int)ceilf (box.w * 56.0f);
    const int Lx = x2 - x1, Ly = y2 - y1;
    const int frac3 = x1 & 3;             // offset from 4-half-aligned base
    const int cp0q  = x1 >> 2;            // H4-unit base within row (<= 6)

    unsigned long long ysP = 0, nP = 0, xsP = 0, xeP = 0;
    for (int j = 0; j < OUT_D; j++) {
        const int ys = y1 + (j * Ly) / 7;
        const int ye = y1 + ((j + 1) * Ly + 6) / 7;     // ceil div, ye > ys
        ysP |= (unsigned long long)ys << (8 * j);
        nP  |= (unsigned long long)(ye - ys) << (8 * j);
        const int xs = (j * Lx) / 7 + frac3;            // half-index in colmax
        const int xe = ((j + 1) * Lx + 6) / 7 + frac3;  // <= 59 < 64
        xsP |= (unsigned long long)xs << (8 * j);
        xeP |= (unsigned long long)xe << (8 * j);
    }
    const int narrow = (frac3 + Lx) <= 32;
    const int key = Ly + (narrow ? 0 : 57);             // cost key < 128

    atomicAdd(&hist[img][key], 1);
    __syncthreads();
    if (tid < 8) {                        // descending prefix (big keys first)
        int off = 0;
        for (int v = 127; v >= 0; v--) { int t = hist[tid][v]; hist[tid][v] = off; off += t; }
    }
    __syncthreads();
    const int pos = base[img] + atomicAdd(&hist[img][key], 1);
    g_meta[pos] = tid | (cp0q << 16) | (narrow << 24);
    g_ybin[pos] = make_ulonglong2(ysP, nP);
    g_xbin[pos] = make_ulonglong2(xsP, xeP);
}

__device__ __forceinline__ int bget(unsigned long long p, int i) {
    return (int)((p >> (8 * i)) & 0xFF);
}

struct __align__(8) H4 { __half2 a, b; };

__device__ __forceinline__ H4 h4max(H4 x, H4 y) {
    x.a = __hmax2(x.a, y.a);
    x.b = __hmax2(x.b, y.b);
    return x;
}

__global__ __launch_bounds__(256, 7)
void roipool_kernel(float* __restrict__ out)
{
    // 2-channel fp16 plane staged from g_plane (+32 H4 pad for overread)
    __shared__ __align__(16) H4      planeS[2 * PLANE_H4 + 32];          // 14592 B
    // colmax: ch0 block, pad 16 words, ch1 block (+16-bank stagger)
    __shared__ __align__(16) __half2 colmaxA[2 * 8 * OUT_D * 32 + 16];   // 14400 B

    const int bid  = blockIdx.x;          // ((b*64 + cp) << 1) | half
    const int half = bid & 1;
    const int bc   = bid >> 1;
    const int b    = bc >> 6;
    const int c0   = (bc & 63) * 2;

    const int tid  = threadIdx.x;
    const int warp = tid >> 5;
    const int lane = tid & 31;

    // Stage both channel planes: 2*896 H4 = 896 uint4, 3.5 per thread.
    {
        const uint4* gsrc = reinterpret_cast<const uint4*>(g_plane)
                            + (size_t)(b * 128 + c0) * (PLANE_H4 / 2);
        uint4* sdst = reinterpret_cast<uint4*>(planeS);
        for (int i = tid; i < PLANE_H4; i += 256)       // 896 uint4 for 2 ch
            sdst[i] = __ldg(gsrc + i);
    }
    __half2* cmw  = colmaxA + warp * (OUT_D * 32);
    __half2* cmw1 = colmaxA + 8 * (OUT_D * 32) + 16 + warp * (OUT_D * 32);
    const int s = g_start[b];
    const int e = g_start[b + 1];
    __syncthreads();

    // 16-way deal over the descending-sorted segment (LPT balance).
    for (int k = s + warp * 2 + half; k < e; k += 16) {
        const int meta = g_meta[k];
        const ulonglong2 yb = g_ybin[k];
        const int cp0q   = (meta >> 16) & 0xFF;
        const int narrow =  meta >> 24;

        // Unified lane mapping: narrow = 8 H4-lanes/ch (upper half-warp
        // duplicates, store masked); wide = 16 H4-lanes/ch.
        int q, ch;
        bool wr;
        if (narrow) { q = lane & 7;  ch = (lane >> 3) & 1; wr = lane < 16; }
        else        { q = lane & 15; ch = lane >> 4;       wr = true; }

        const H4* baseq = planeS + ch * PLANE_H4 + cp0q + q;
        __half2* cmc = (ch ? cmw1 : cmw) + 2 * q;

        #pragma unroll
        for (int i = 0; i < OUT_D; i++) {
            const int ys = bget(yb.x, i);
            const int n  = bget(yb.y, i);
            const H4* ptr = baseq + ys * ROWH4;
            H4 m = ptr[0];                            // peel (bin non-empty)
            int rem = n - 1;
            ptr += ROWH4;
            while (rem >= 2) {                        // unroll 2
                m = h4max(h4max(m, ptr[0]), ptr[ROWH4]);
                ptr += 2 * ROWH4;
                rem -= 2;
            }
            if (rem) m = h4max(m, ptr[0]);
            if (wr) {
                cmc[i * 32]     = m.a;
                cmc[i * 32 + 1] = m.b;
            }
        }
        __syncwarp();

        // ---- Pass 2: 49 outputs x 2 channels; shared index math ----
        const ulonglong2 xb = g_xbin[k];
        const int r = meta & 0xFFFF;
        float* outr = out + ((size_t)r * 128 + c0) * (OUT_D * OUT_D);
        #pragma unroll
        for (int bs = 0; bs < 64; bs += 32) {
            const int o = bs + lane;
            if (o < OUT_D * OUT_D) {
                const int i  = (o * 37) >> 8;         // o/7 for o<49
                const int j  = o - i * 7;
                const int xs = bget(xb.x, j);
                const int xe = bget(xb.y, j);
                const __half* cA = reinterpret_cast<const __half*>(cmw  + i * 32);
                const __half* cB = reinterpret_cast<const __half*>(cmw1 + i * 32);
                __half m0 = cA[xs];
                __half m1 = cB[xs];
                for (int x = xs + 1; x < xe; x++) {
                    m0 = __hmax(m0, cA[x]);
                    m1 = __hmax(m1, cB[x]);
                }
                outr[o]      = __half2float(m0);
                outr[o + 49] = __half2float(m1);
            }
        }
        __syncwarp();   // protect colmax before next ROI's pass 1
    }
}

extern "C" void kernel_launch(void* const* d_in, const int* in_sizes, int n_in,
                              void* d_out, int out_size)
{
    const float* images  = (const float*)d_in[0];   // [8,128,56,56]
    const float* rois    = (const float*)d_in[1];   // [512,4]
    const int*   roi_idx = (const int*)  d_in[2];   // [512]
    float*       out     = (float*)d_out;           // [512,128,7,7]

    // blocks 0..783: convert (784*512*2 = 802816 float4); block 784: prep
    prep_convert_kernel<<<785, 512>>>(images, rois, roi_idx);
    roipool_kernel<<<8 * 64 * 2, 256>>>(out);
}

// round 17
// speedup vs baseline: 1.1627x; 1.1627x over previous
#include <cuda_runtime.h>
#include <cuda_fp16.h>
#include <math.h>

// SlowROIPool R17: R16 + bank-conflict fixes (layout only).
//  - colmax bin stride 32 -> 34 words: pass-2 scalar LDS was 4-5-way
//    conflicted (bin stride ≡ 0 mod 32 banks -> same-j lanes same bank).
//  - ch1 colmax block at 8*238 words ≡ 16 mod 32: narrow STS phases disjoint.
//  - ch1 plane base +8 H4 (≡16 mod 32): narrow pass-1 LDS phase conflict-free.
// images: [8,128,56,56] f32, rois: [512,4] f32, roi_idx: [512] i32,
// out: [512,128,7,7] f32.

#define OUT_D 7
#define ROWH4    16                 // H4 (8B) units per plane row (64 halves)
#define PLANE_H4 (56 * ROWH4)       // 896 H4 units per (b,c) plane
#define PL_CH1   (PLANE_H4 + 8)     // ch1 smem plane base (≡16 words mod 32)
#define CMBIN 34                    // colmax words per bin (even; 2i bank skew)
#define CMCH  (OUT_D * CMBIN)       // 238 words per (warp, channel)

// fp16 planes: 1024 planes x 56 rows x 64 halves (+pad for overread)
__device__ __align__(16) unsigned long long g_plane[1024 * PLANE_H4 + 32];

__device__ int        g_meta[512];  // roi | cp0q<<16 | narrow<<24
__device__ ulonglong2 g_ybin[512];  // {ysP, nP}: byte i = ys / row-count of y-bin i
__device__ ulonglong2 g_xbin[512];  // {xsP, xeP}: byte j = half-index bounds (frac3-based)
__device__ int        g_start[9];   // per-image segment starts

// ---- fused: fp32->fp16 conversion (blocks 0..783, 2 float4/thread) + prep ----
__global__ void prep_convert_kernel(const float* __restrict__ images,
                                    const float* __restrict__ rois,
                                    const int*   __restrict__ roi_idx)
{
    if (blockIdx.x < 784) {
        // 784 blocks x 512 threads x 2 = 802816 float4 (exact)
        const int j0 = blockIdx.x * 1024 + threadIdx.x;
        #pragma unroll
        for (int t = 0; t < 2; t++) {
            const int j = j0 + t * 512;
            float4 v = reinterpret_cast<const float4*>(images)[j];
            const int r  = j / 14;                  // global row = plane*56 + y
            const int c4 = j - r * 14;
            __half2 lo = __floats2half2_rn(v.x, v.y);
            __half2 hi = __floats2half2_rn(v.z, v.w);
            uint2 w;
            w.x = *reinterpret_cast<unsigned*>(&lo);
            w.y = *reinterpret_cast<unsigned*>(&hi);
            reinterpret_cast<uint2*>(g_plane)[r * ROWH4 + c4] = w;
        }
        return;
    }

    // ---- prep (block 784, 512 threads) ----
    __shared__ int cnt[8];
    __shared__ int base[8];
    __shared__ int hist[8][128];
    const int tid = threadIdx.x;
    if (tid < 8) cnt[tid] = 0;
    for (int i = tid; i < 8 * 128; i += 512) (&hist[0][0])[i] = 0;
    __syncthreads();
    const int img = roi_idx[tid];
    atomicAdd(&cnt[img], 1);
    __syncthreads();
    if (tid == 0) {
        int acc = 0;
        for (int i = 0; i < 8; i++) { base[i] = acc; g_start[i] = acc; acc += cnt[i]; }
        g_start[8] = acc;
    }
    __syncthreads();

    const float4 box = reinterpret_cast<const float4*>(rois)[tid];
    // Match jnp: fp32 floor/ceil then int cast.
    const int x1 = (int)floorf(box.x * 56.0f);
    const int y1 = (int)floorf(box.y * 56.0f);
    const int x2 = (int)ceilf (box.z * 56.0f);
    const int y2 = (int)ceilf (box.w * 56.0f);
    const int Lx = x2 - x1, Ly = y2 - y1;
    const int frac3 = x1 & 3;             // offset from 4-half-aligned base
    const int cp0q  = x1 >> 2;            // H4-unit base within row (<= 6)

    unsigned long long ysP = 0, nP = 0, xsP = 0, xeP = 0;
    for (int j = 0; j < OUT_D; j++) {
        const int ys = y1 + (j * Ly) / 7;
        const int ye = y1 + ((j + 1) * Ly + 6) / 7;     // ceil div, ye > ys
        ysP |= (unsigned long long)ys << (8 * j);
        nP  |= (unsigned long long)(ye - ys) << (8 * j);
        const int xs = (j * Lx) / 7 + frac3;            // half-index in colmax
        const int xe = ((j + 1) * Lx + 6) / 7 + frac3;  // <= 59 < 68
        xsP |= (unsigned long long)xs << (8 * j);
        xeP |= (unsigned long long)xe << (8 * j);
    }
    const int narrow = (frac3 + Lx) <= 32;
    const int key = Ly + (narrow ? 0 : 57);             // cost key < 128

    atomicAdd(&hist[img][key], 1);
    __syncthreads();
    if (tid < 8) {                        // descending prefix (big keys first)
        int off = 0;
        for (int v = 127; v >= 0; v--) { int t = hist[tid][v]; hist[tid][v] = off; off += t; }
    }
    __syncthreads();
    const int pos = base[img] + atomicAdd(&hist[img][key], 1);
    g_meta[pos] = tid | (cp0q << 16) | (narrow << 24);
    g_ybin[pos] = make_ulonglong2(ysP, nP);
    g_xbin[pos] = make_ulonglong2(xsP, xeP);
}

__device__ __forceinline__ int bget(unsigned long long p, int i) {
    return (int)((p >> (8 * i)) & 0xFF);
}

struct __align__(8) H4 { __half2 a, b; };

__device__ __forceinline__ H4 h4max(H4 x, H4 y) {
    x.a = __hmax2(x.a, y.a);
    x.b = __hmax2(x.b, y.b);
    return x;
}

__global__ __launch_bounds__(256, 7)
void roipool_kernel(float* __restrict__ out)
{
    // ch0 plane [0,896), ch1 plane [904,1800) (+32 H4 slack for overread)
    __shared__ __align__(16) H4      planeS[PL_CH1 + PLANE_H4 + 32];     // 14656 B
    // colmax: ch0 warps at warp*CMCH; ch1 block base 8*CMCH=1904 ≡ 16 mod 32
    __shared__ __align__(16) __half2 colmaxA[16 * CMCH];                 // 15232 B

    const int bid  = blockIdx.x;          // ((b*64 + cp) << 1) | half
    const int half = bid & 1;
    const int bc   = bid >> 1;
    const int b    = bc >> 6;
    const int c0   = (bc & 63) * 2;

    const int tid  = threadIdx.x;
    const int warp = tid >> 5;
    const int lane = tid & 31;

    // Stage both channel planes: 896 uint4; ch1 shifted by 4 uint4 (8 H4).
    {
        const uint4* gsrc = reinterpret_cast<const uint4*>(g_plane)
                            + (size_t)(b * 128 + c0) * (PLANE_H4 / 2);
        uint4* sdst = reinterpret_cast<uint4*>(planeS);
        for (int i = tid; i < PLANE_H4; i += 256)       // 896 uint4 for 2 ch
            sdst[i + (i >= PLANE_H4 / 2 ? 4 : 0)] = __ldg(gsrc + i);
    }
    __half2* cmw  = colmaxA + warp * CMCH;
    __half2* cmw1 = colmaxA + 8 * CMCH + warp * CMCH;
    const int s = g_start[b];
    const int e = g_start[b + 1];
    __syncthreads();

    // 16-way deal over the descending-sorted segment (LPT balance).
    for (int k = s + warp * 2 + half; k < e; k += 16) {
        const int meta = g_meta[k];
        const ulonglong2 yb = g_ybin[k];
        const int cp0q   = (meta >> 16) & 0xFF;
        const int narrow =  meta >> 24;

        // Unified lane mapping: narrow = 8 H4-lanes/ch (upper half-warp
        // duplicates, store masked); wide = 16 H4-lanes/ch.
        int q, ch;
        bool wr;
        if (narrow) { q = lane & 7;  ch = (lane >> 3) & 1; wr = lane < 16; }
        else        { q = lane & 15; ch = lane >> 4;       wr = true; }

        const H4* baseq = planeS + (ch ? PL_CH1 : 0) + cp0q + q;
        __half2* cmc = (ch ? cmw1 : cmw) + 2 * q;

        #pragma unroll
        for (int i = 0; i < OUT_D; i++) {
            const int ys = bget(yb.x, i);
            const int n  = bget(yb.y, i);
            const H4* ptr = baseq + ys * ROWH4;
            H4 m = ptr[0];                            // peel (bin non-empty)
            int rem = n - 1;
            ptr += ROWH4;
            while (rem >= 2) {                        // unroll 2
                m = h4max(h4max(m, ptr[0]), ptr[ROWH4]);
                ptr += 2 * ROWH4;
                rem -= 2;
            }
            if (rem) m = h4max(m, ptr[0]);
            if (wr) {
                cmc[i * CMBIN]     = m.a;
                cmc[i * CMBIN + 1] = m.b;
            }
        }
        __syncwarp();

        // ---- Pass 2: 49 outputs x 2 channels; shared index math ----
        const ulonglong2 xb = g_xbin[k];
        const int r = meta & 0xFFFF;
        float* outr = out + ((size_t)r * 128 + c0) * (OUT_D * OUT_D);
        #pragma unroll
        for (int bs = 0; bs < 64; bs += 32) {
            const int o = bs + lane;
            if (o < OUT_D * OUT_D) {
                const int i  = (o * 37) >> 8;         // o/7 for o<49
                const int j  = o - i * 7;
                const int xs = bget(xb.x, j);
                const int xe = bget(xb.y, j);
                const __half* cA = reinterpret_cast<const __half*>(cmw  + i * CMBIN);
                const __half* cB = reinterpret_cast<const __half*>(cmw1 + i * CMBIN);
                __half m0 = cA[xs];
                __half m1 = cB[xs];
                for (int x = xs + 1; x < xe; x++) {
                    m0 = __hmax(m0, cA[x]);
                    m1 = __hmax(m1, cB[x]);
                }
                outr[o]      = __half2float(m0);
                outr[o + 49] = __half2float(m1);
            }
        }
        __syncwarp();   // protect colmax before next ROI's pass 1
    }
}

extern "C" void kernel_launch(void* const* d_in, const int* in_sizes, int n_in,
                              void* d_out, int out_size)
{
    const float* images  = (const float*)d_in[0];   // [8,128,56,56]
    const float* rois    = (const float*)d_in[1];   // [512,4]
    const int*   roi_idx = (const int*)  d_in[2];   // [512]
    float*       out     = (float*)d_out;           // [512,128,7,7]

    // blocks 0..783: convert (784*512*2 = 802816 float4); block 784: prep
    prep_convert_kernel<<<785, 512>>>(images, rois, roi_idx);
    roipool_kernel<<<8 * 64 * 2, 256>>>(out);
}